// round 10
// baseline (speedup 1.0000x reference)
#include <cuda_runtime.h>
#include <math.h>

#define Bb 8
#define Nn 3072
#define IN_D 3
#define HD 64
#define Kk 16
#define Ll 2

// ---------------- scratch (device globals: the sanctioned no-alloc path) ----
__device__ float g_h [Bb*Nn*HD];          // 6.3 MB
__device__ float g_hn[Bb*Nn*HD];          // 6.3 MB
__device__ float g_xx[Bb*Nn];             // 98 KB
__device__ int   g_idx[Bb*Nn*Kk];         // 1.6 MB

__device__ __forceinline__ float elu1(float v) { return v > 0.f ? v : expm1f(v); }

// ---------------- f32x2 packed-FMA helpers (SASS FFMA2: 2x fp32 per issue) --
typedef unsigned long long u64t;
__device__ __forceinline__ u64t dup2(float x) {
    u64t r; asm("mov.b64 %0, {%1, %2};" : "=l"(r) : "f"(x), "f"(x)); return r;
}
__device__ __forceinline__ u64t fma2(u64t a, u64t b, u64t c) {
    u64t d; asm("fma.rn.f32x2 %0, %1, %2, %3;" : "=l"(d) : "l"(a), "l"(b), "l"(c)); return d;
}
__device__ __forceinline__ float2 unpack2(u64t v) {
    float2 r; asm("mov.b64 {%0, %1}, %2;" : "=f"(r.x), "=f"(r.y) : "l"(v)); return r;
}

__device__ __forceinline__ unsigned long long u64min(unsigned long long a, unsigned long long b) {
    return a < b ? a : b;
}
__device__ __forceinline__ unsigned long long u64max(unsigned long long a, unsigned long long b) {
    return a > b ? a : b;
}

// ---------------- K1: input embedding --------------------------------------
__global__ void embed_kernel(const float* __restrict__ x, const float* __restrict__ dn,
                             const float* __restrict__ Win, const float* __restrict__ bin,
                             float* __restrict__ h) {
    int t = blockIdx.x * 256 + threadIdx.x;
    if (t >= Bb*Nn*HD) return;
    int c = t & 63, p = t >> 6;
    float a = bin[c];
#pragma unroll
    for (int i = 0; i < IN_D; i++) a = fmaf(x[p*IN_D + i] * dn[i], Win[i*HD + c], a);
    h[t] = elu1(a);
}

// ---------------- K2: row squared norms -------------------------------------
__global__ void xx_kernel(const float* __restrict__ h, float* __restrict__ xx) {
    int gw = (blockIdx.x * 256 + threadIdx.x) >> 5;
    int lane = threadIdx.x & 31;
    if (gw >= Bb*Nn) return;
    float2 v = ((const float2*)(h + (size_t)gw * HD))[lane];
    float s = fmaf(v.x, v.x, v.y * v.y);
#pragma unroll
    for (int o = 16; o > 0; o >>= 1) s += __shfl_xor_sync(0xffffffffu, s, o);
    if (lane == 0) xx[gw] = s;
}

// ---------------- K3: fused distance GEMM + top-16 (no D materialization) ---
// Block = 128 threads (4 warps). i-tile = 64 rows, j-tile = 128 cols.
// Per j-tile: GEMM (f32x2 packed) -> smem distance tile -> per-warp bitonic
// running-queue top-k update (identical algorithm/keys to the standalone
// kernel; queue state in smem between tiles).
// smem floats: sA 64*64=4096, sB 16*128=2048, sD 64*132=8448, sQ 2048 u64=4096
#define DT_SMEM_FLOATS (4096 + 2048 + 8448 + 4096)
#define DT_SMEM_BYTES  (DT_SMEM_FLOATS * 4)

__global__ __launch_bounds__(128, 3) void dist_topk_kernel(
    const float* __restrict__ h, const float* __restrict__ xx,
    int* __restrict__ idxout) {
    extern __shared__ float sm[];
    float* sA = sm;               // [64][64]   i-rows x k
    float* sB = sA + 4096;        // [16][128]  k x j
    float* sD = sB + 2048;        // [64][132]  distance tile (padded)
    u64t*  sQ = (u64t*)(sD + 8448);  // [64][32] per-row sorted queue

    const unsigned FULL = 0xffffffffu;
    const unsigned long long UMAX = 0xFFFFFFFFFFFFFFFFull;

    int b = blockIdx.y;
    int i0 = blockIdx.x * 64;
    const float* hb = h + (size_t)b * Nn * HD;
    int tid = threadIdx.x;
    int tx = tid & 15, ty = tid >> 4;       // 16 x 8 thread grid
    int lane = tid & 31, w = tid >> 5;      // 4 warps

    // load A tile (64 rows x 64 k) once
    for (int f = tid; f < 1024; f += 128) {
        int r = f >> 4, k4 = (f & 15) << 2;
        float4 v = *(const float4*)&hb[(i0 + r)*HD + k4];
        sA[r*64 + k4+0] = v.x; sA[r*64 + k4+1] = v.y;
        sA[r*64 + k4+2] = v.z; sA[r*64 + k4+3] = v.w;
    }
    // init queues
    for (int f = tid; f < 2048; f += 128) sQ[f] = UMAX;

    float xi[8];
#pragma unroll
    for (int u = 0; u < 8; u++) xi[u] = xx[b*Nn + i0 + ty*8 + u];

    for (int jt = 0; jt < Nn/128; jt++) {
        int j0 = jt * 128;

        u64t accp[8][4];
#pragma unroll
        for (int u = 0; u < 8; u++)
#pragma unroll
            for (int v = 0; v < 4; v++) accp[u][v] = 0ull;

        for (int k0 = 0; k0 < HD; k0 += 16) {
            __syncthreads();
            // load B chunk: 128 j-rows x 16 k, transposed to [k][j]
            for (int f = tid; f < 512; f += 128) {
                int rj = f >> 2, rk = (f & 3) << 2;
                float4 vb = *(const float4*)&hb[(j0 + rj)*HD + k0 + rk];
                sB[(rk+0)*128 + rj] = vb.x; sB[(rk+1)*128 + rj] = vb.y;
                sB[(rk+2)*128 + rj] = vb.z; sB[(rk+3)*128 + rj] = vb.w;
            }
            __syncthreads();
#pragma unroll
            for (int k = 0; k < 16; k++) {
                u64t a2[8];
#pragma unroll
                for (int u = 0; u < 8; u++) a2[u] = dup2(sA[(ty*8 + u)*64 + k0 + k]);
                ulonglong2 q0 = *(const ulonglong2*)&sB[k*128 + tx*8];
                ulonglong2 q1 = *(const ulonglong2*)&sB[k*128 + tx*8 + 4];
                u64t bp[4] = {q0.x, q0.y, q1.x, q1.y};
#pragma unroll
                for (int u = 0; u < 8; u++)
#pragma unroll
                    for (int v = 0; v < 4; v++) accp[u][v] = fma2(a2[u], bp[v], accp[u][v]);
            }
        }

        // epilogue: distances into sD
        float xj[8];
#pragma unroll
        for (int v = 0; v < 8; v++) xj[v] = xx[b*Nn + j0 + tx*8 + v];
#pragma unroll
        for (int u = 0; u < 8; u++) {
            float2 c0 = unpack2(accp[u][0]);
            float2 c1 = unpack2(accp[u][1]);
            float2 c2 = unpack2(accp[u][2]);
            float2 c3 = unpack2(accp[u][3]);
            float* dr = &sD[(ty*8 + u)*132 + tx*8];
            float4 o0, o1;
            o0.x = xi[u] + xj[0] - 2.f*c0.x;
            o0.y = xi[u] + xj[1] - 2.f*c0.y;
            o0.z = xi[u] + xj[2] - 2.f*c1.x;
            o0.w = xi[u] + xj[3] - 2.f*c1.y;
            o1.x = xi[u] + xj[4] - 2.f*c2.x;
            o1.y = xi[u] + xj[5] - 2.f*c2.y;
            o1.z = xi[u] + xj[6] - 2.f*c3.x;
            o1.w = xi[u] + xj[7] - 2.f*c3.y;
            *(float4*)&dr[0] = o0;
            *(float4*)&dr[4] = o1;
        }
        __syncthreads();

        // top-k phase: warp w owns rows w*16 .. w*16+15
        for (int r = 0; r < 16; r++) {
            int row = (w << 4) + r;
            float4 dv = *(const float4*)&sD[row*132 + lane*4];
            float ds[4] = {dv.x, dv.y, dv.z, dv.w};
            unsigned long long wq = sQ[row*32 + lane];
            unsigned long long kth = __shfl_sync(FULL, wq, 15);
            bool touched = false;
#pragma unroll
            for (int s = 0; s < 4; s++) {
                int j = j0 + lane*4 + s;
                unsigned u = __float_as_uint(ds[s]);
                u ^= (unsigned)(((int)u >> 31)) | 0x80000000u;   // monotone float->uint
                unsigned long long key = ((unsigned long long)u << 32) | (unsigned)j;

                bool act = key < kth;
                if (__ballot_sync(FULL, act)) {
                    unsigned long long c = act ? key : UMAX;
                    // bitonic full sort of candidate batch, ascending across lanes
#pragma unroll
                    for (int kk = 2; kk <= 32; kk <<= 1) {
#pragma unroll
                        for (int jj = kk >> 1; jj >= 1; jj >>= 1) {
                            unsigned long long p = __shfl_xor_sync(FULL, c, jj);
                            bool up = ((lane & kk) == 0);
                            bool keepmin = (((lane & jj) == 0) == up);
                            c = keepmin ? u64min(c, p) : u64max(c, p);
                        }
                    }
                    // bitonic merge: keep smallest 32 of (sorted wq, sorted c)
                    unsigned long long rev = __shfl_sync(FULL, c, 31 - lane);
                    unsigned long long v = u64min(wq, rev);
#pragma unroll
                    for (int off = 16; off >= 1; off >>= 1) {
                        unsigned long long p = __shfl_xor_sync(FULL, v, off);
                        v = ((lane & off) == 0) ? u64min(v, p) : u64max(v, p);
                    }
                    wq = v;
                    kth = __shfl_sync(FULL, wq, 15);
                    touched = true;
                }
            }
            if (touched) sQ[row*32 + lane] = wq;
        }
        __syncthreads();
    }

    // output: lanes 0..15 of each row's queue = sorted top-16 indices
    for (int r = 0; r < 16; r++) {
        int row = (w << 4) + r;
        if (lane < Kk) {
            unsigned long long q = sQ[row*32 + lane];
            idxout[((size_t)b*Nn + i0 + row)*Kk + lane] = (int)(q & 0xFFFFFFFFull);
        }
    }
}

// ---------------- K5: fused edge MLP (8 points = 128 edges per block) -------
// smem: W1(16384) W2(8192) Msg(128x132=16896) M1(128x128=16384) b1(128) b2(64)
#define EDGE_SMEM_FLOATS (16384 + 8192 + 16896 + 16384 + 128 + 64)
#define EDGE_SMEM_BYTES  (EDGE_SMEM_FLOATS * 4)

__global__ __launch_bounds__(256, 1) void edge_mlp_kernel(
    const float* __restrict__ h, const int* __restrict__ nidx,
    const float* __restrict__ W1, const float* __restrict__ b1,
    const float* __restrict__ W2, const float* __restrict__ b2,
    float* __restrict__ hout) {
    extern __shared__ float sm[];
    float* sW1  = sm;                  // 128x128
    float* sW2  = sW1 + 16384;         // 128x64
    float* sMsg = sW2 + 8192;          // 128 edges x 132 (padded)
    float* sM1  = sMsg + 16896;        // 128 edges x 128
    float* sb1  = sM1 + 16384;
    float* sb2  = sb1 + 128;
    int*   sIdx = (int*)sM1;           // alias: dead before first sM1 write
    float* sHn  = sMsg;                // alias: dead after GEMM1 reads finish

    int tid = threadIdx.x;
    int b = blockIdx.y;
    int p0 = blockIdx.x * 8;
    const float* hb = h + (size_t)b * Nn * HD;

    // cooperative weight / idx loads
    {
        const float4* w1v = (const float4*)W1;
        float4* s1v = (float4*)sW1;
        for (int f = tid; f < 4096; f += 256) s1v[f] = w1v[f];
        const float4* w2v = (const float4*)W2;
        float4* s2v = (float4*)sW2;
        for (int f = tid; f < 2048; f += 256) s2v[f] = w2v[f];
        if (tid < 128) sb1[tid] = b1[tid];
        if (tid < 64)  sb2[tid] = b2[tid];
        if (tid < 128) sIdx[tid] = nidx[((size_t)b*Nn + p0)*Kk + tid];
    }
    __syncthreads();

    // assemble msg = [x_i | x_j - x_i] per edge (float4 per thread-iter)
    for (int f = tid; f < 4096; f += 256) {
        int e = f >> 5, q = f & 31;               // 32 float4 per edge row
        int p = p0 + (e >> 4);
        float4 v;
        if (q < 16) {
            v = *(const float4*)&hb[p*HD + q*4];
        } else {
            int j = sIdx[e];
            float4 aj = *(const float4*)&hb[j*HD + (q-16)*4];
            float4 ai = *(const float4*)&hb[p*HD + (q-16)*4];
            v = make_float4(aj.x-ai.x, aj.y-ai.y, aj.z-ai.z, aj.w-ai.w);
        }
        *(float4*)&sMsg[e*132 + q*4] = v;
    }
    __syncthreads();

    int tx = tid & 15, ty = tid >> 4;

    // GEMM1: m1 = elu(msg @ W1 + b1)   (128 x 128 x 128), f32x2 packed
    u64t accp[8][4];
#pragma unroll
    for (int u = 0; u < 8; u++)
#pragma unroll
        for (int v = 0; v < 4; v++) accp[u][v] = 0ull;
    {
        const float* aB = sMsg + (ty*4)*132;   // rows ty*4..+3 and +64..+67
#pragma unroll 4
        for (int k = 0; k < 128; k++) {
            u64t a2[8];
#pragma unroll
            for (int u = 0; u < 4; u++) a2[u]   = dup2(aB[u*132 + k]);
#pragma unroll
            for (int u = 0; u < 4; u++) a2[4+u] = dup2(aB[(64+u)*132 + k]);
            ulonglong2 q0 = *(const ulonglong2*)&sW1[k*128 + tx*8];
            ulonglong2 q1 = *(const ulonglong2*)&sW1[k*128 + tx*8 + 4];
            u64t bp[4] = {q0.x, q0.y, q1.x, q1.y};
#pragma unroll
            for (int u = 0; u < 8; u++)
#pragma unroll
                for (int v = 0; v < 4; v++) accp[u][v] = fma2(a2[u], bp[v], accp[u][v]);
        }
    }
    // epilogue -> sM1 (row-major, stride 128)
#pragma unroll
    for (int u = 0; u < 8; u++) {
        int r = ty*4 + (u & 3) + ((u >> 2) << 6);
        float2 c0 = unpack2(accp[u][0]);
        float2 c1 = unpack2(accp[u][1]);
        float2 c2 = unpack2(accp[u][2]);
        float2 c3 = unpack2(accp[u][3]);
        float4 s0, s1;
        s0.x = elu1(c0.x + sb1[tx*8+0]);
        s0.y = elu1(c0.y + sb1[tx*8+1]);
        s0.z = elu1(c1.x + sb1[tx*8+2]);
        s0.w = elu1(c1.y + sb1[tx*8+3]);
        s1.x = elu1(c2.x + sb1[tx*8+4]);
        s1.y = elu1(c2.y + sb1[tx*8+5]);
        s1.z = elu1(c3.x + sb1[tx*8+6]);
        s1.w = elu1(c3.y + sb1[tx*8+7]);
        *(float4*)&sM1[r*128 + tx*8]     = s0;
        *(float4*)&sM1[r*128 + tx*8 + 4] = s1;
    }
    __syncthreads();           // sM1 complete, sMsg reads done
    sHn[tid] = 0.f; sHn[tid + 256] = 0.f;
    __syncthreads();

    // GEMM2: m2 = elu(m1 @ W2 + b2), summed over K=16 edges per point (f32x2)
    u64t accp2[8][2];
#pragma unroll
    for (int u = 0; u < 8; u++)
#pragma unroll
        for (int v = 0; v < 2; v++) accp2[u][v] = 0ull;
    {
        const float* aB = sM1 + (ty*4)*128;
#pragma unroll 4
        for (int k = 0; k < 128; k++) {
            u64t a2[8];
#pragma unroll
            for (int u = 0; u < 4; u++) a2[u]   = dup2(aB[u*128 + k]);
#pragma unroll
            for (int u = 0; u < 4; u++) a2[4+u] = dup2(aB[(64+u)*128 + k]);
            ulonglong2 q = *(const ulonglong2*)&sW2[k*64 + tx*4];
            u64t bp[2] = {q.x, q.y};
#pragma unroll
            for (int u = 0; u < 8; u++)
#pragma unroll
                for (int v = 0; v < 2; v++) accp2[u][v] = fma2(a2[u], bp[v], accp2[u][v]);
        }
    }
    {
        int pA = ty >> 2;     // rows ty*4.. within point ty/4 ; +64 -> point +4
#pragma unroll
        for (int half = 0; half < 2; half++) {
            int p = pA + half*4;
#pragma unroll
            for (int vp = 0; vp < 2; vp++) {
                float slo = 0.f, shi = 0.f;
#pragma unroll
                for (int u0 = 0; u0 < 4; u0++) {
                    float2 c = unpack2(accp2[half*4 + u0][vp]);
                    slo += elu1(c.x + sb2[tx*4 + 2*vp]);
                    shi += elu1(c.y + sb2[tx*4 + 2*vp + 1]);
                }
                atomicAdd(&sHn[p*64 + tx*4 + 2*vp],     slo);
                atomicAdd(&sHn[p*64 + tx*4 + 2*vp + 1], shi);
            }
        }
    }
    __syncthreads();
    for (int f = tid; f < 512; f += 256) {
        int p = f >> 6, c = f & 63;
        hout[((size_t)b*Nn + p0 + p)*HD + c] = sHn[f];
    }
}

// ---------------- K6: max-pool + 3-layer head -------------------------------
__global__ __launch_bounds__(256) void pool_head_kernel(const float* __restrict__ h,
    const float* __restrict__ Wo1, const float* __restrict__ bo1,
    const float* __restrict__ Wo2, const float* __restrict__ bo2,
    const float* __restrict__ Wo3, const float* __restrict__ bo3,
    float* __restrict__ out) {
    __shared__ float red[256];
    __shared__ float sp[64];
    __shared__ float so[64];
    int b = blockIdx.x, tid = threadIdx.x;
    int c = tid & 63, g = tid >> 6;
    const float* hb = h + (size_t)b * Nn * HD;
    float m = -3.402823e38f;
    for (int n = g; n < Nn; n += 4) m = fmaxf(m, hb[n*HD + c]);
    red[tid] = m;
    __syncthreads();
    if (tid < 64)
        sp[tid] = fmaxf(fmaxf(red[tid], red[tid+64]), fmaxf(red[tid+128], red[tid+192]));
    __syncthreads();
    if (tid < 64) {
        float a = bo1[tid];
#pragma unroll 8
        for (int d = 0; d < 64; d++) a = fmaf(sp[d], Wo1[d*64 + tid], a);
        so[tid] = elu1(a);
    }
    __syncthreads();
    if (tid < 64) {
        float a = bo2[tid];
#pragma unroll 8
        for (int d = 0; d < 64; d++) a = fmaf(so[d], Wo2[d*64 + tid], a);
        red[tid] = elu1(a);
    }
    __syncthreads();
    if (tid == 0) {
        float a = bo3[0];
#pragma unroll 8
        for (int d = 0; d < 64; d++) a = fmaf(red[d], Wo3[d], a);
        out[b] = a;
    }
}

// ---------------- launcher --------------------------------------------------
extern "C" void kernel_launch(void* const* d_in, const int* in_sizes, int n_in,
                              void* d_out, int out_size) {
    const float* x   = (const float*)d_in[0];
    const float* dn  = (const float*)d_in[1];
    const float* Win = (const float*)d_in[2];
    const float* bin = (const float*)d_in[3];
    const float* W1  = (const float*)d_in[4];
    const float* b1  = (const float*)d_in[5];
    const float* W2  = (const float*)d_in[6];
    const float* b2  = (const float*)d_in[7];
    const float* Wo1 = (const float*)d_in[8];
    const float* bo1 = (const float*)d_in[9];
    const float* Wo2 = (const float*)d_in[10];
    const float* bo2 = (const float*)d_in[11];
    const float* Wo3 = (const float*)d_in[12];
    const float* bo3 = (const float*)d_in[13];
    float* out = (float*)d_out;

    float *ph, *phn, *pxx; int* pidx;
    cudaGetSymbolAddress((void**)&ph,  g_h);
    cudaGetSymbolAddress((void**)&phn, g_hn);
    cudaGetSymbolAddress((void**)&pxx, g_xx);
    cudaGetSymbolAddress((void**)&pidx, g_idx);

    cudaFuncSetAttribute(edge_mlp_kernel,
                         cudaFuncAttributeMaxDynamicSharedMemorySize, EDGE_SMEM_BYTES);
    cudaFuncSetAttribute(dist_topk_kernel,
                         cudaFuncAttributeMaxDynamicSharedMemorySize, DT_SMEM_BYTES);

    embed_kernel<<<(Bb*Nn*HD + 255)/256, 256>>>(x, dn, Win, bin, ph);

    for (int l = 0; l < Ll; l++) {
        const float* hin = (l == 0) ? ph : phn;
        float* hout      = (l == 0) ? phn : ph;
        xx_kernel<<<Bb*Nn/8, 256>>>(hin, pxx);
        dist_topk_kernel<<<dim3(Nn/64, Bb), 128, DT_SMEM_BYTES>>>(hin, pxx, pidx);
        edge_mlp_kernel<<<dim3(Nn/8, Bb), 256, EDGE_SMEM_BYTES>>>(
            hin, pidx, W1 + l*2*HD*2*HD, b1 + l*2*HD, W2 + l*2*HD*HD, b2 + l*HD, hout);
    }

    pool_head_kernel<<<Bb, 256>>>(ph, Wo1, bo1, Wo2, bo2, Wo3, bo3, out);
}

// round 11
// speedup vs baseline: 1.1797x; 1.1797x over previous
#include <cuda_runtime.h>
#include <math.h>

#define Bb 8
#define Nn 3072
#define IN_D 3
#define HD 64
#define Kk 16
#define Ll 2

// ---------------- scratch (device globals: the sanctioned no-alloc path) ----
__device__ float g_h [Bb*Nn*HD];          // 6.3 MB
__device__ float g_hn[Bb*Nn*HD];          // 6.3 MB
__device__ float g_xx[Bb*Nn];             // 98 KB
__device__ float g_D [Bb*Nn*Nn];          // 302 MB distance matrix
__device__ int   g_idx[Bb*Nn*Kk];         // 1.6 MB

__device__ __forceinline__ float elu1(float v) { return v > 0.f ? v : expm1f(v); }

// ---------------- f32x2 packed-FMA helpers (SASS FFMA2: 2x fp32 per issue) --
typedef unsigned long long u64t;
__device__ __forceinline__ u64t dup2(float x) {
    u64t r; asm("mov.b64 %0, {%1, %2};" : "=l"(r) : "f"(x), "f"(x)); return r;
}
__device__ __forceinline__ u64t fma2(u64t a, u64t b, u64t c) {
    u64t d; asm("fma.rn.f32x2 %0, %1, %2, %3;" : "=l"(d) : "l"(a), "l"(b), "l"(c)); return d;
}
__device__ __forceinline__ float2 unpack2(u64t v) {
    float2 r; asm("mov.b64 {%0, %1}, %2;" : "=f"(r.x), "=f"(r.y) : "l"(v)); return r;
}

__device__ __forceinline__ unsigned long long u64min(unsigned long long a, unsigned long long b) {
    return a < b ? a : b;
}
__device__ __forceinline__ unsigned long long u64max(unsigned long long a, unsigned long long b) {
    return a > b ? a : b;
}

// ---------------- K1: input embedding --------------------------------------
__global__ void embed_kernel(const float* __restrict__ x, const float* __restrict__ dn,
                             const float* __restrict__ Win, const float* __restrict__ bin,
                             float* __restrict__ h) {
    int t = blockIdx.x * 256 + threadIdx.x;
    if (t >= Bb*Nn*HD) return;
    int c = t & 63, p = t >> 6;
    float a = bin[c];
#pragma unroll
    for (int i = 0; i < IN_D; i++) a = fmaf(x[p*IN_D + i] * dn[i], Win[i*HD + c], a);
    h[t] = elu1(a);
}

// ---------------- K2: row squared norms -------------------------------------
__global__ void xx_kernel(const float* __restrict__ h, float* __restrict__ xx) {
    int gw = (blockIdx.x * 256 + threadIdx.x) >> 5;
    int lane = threadIdx.x & 31;
    if (gw >= Bb*Nn) return;
    float2 v = ((const float2*)(h + (size_t)gw * HD))[lane];
    float s = fmaf(v.x, v.x, v.y * v.y);
#pragma unroll
    for (int o = 16; o > 0; o >>= 1) s += __shfl_xor_sync(0xffffffffu, s, o);
    if (lane == 0) xx[gw] = s;
}

// ---------------- K3: distance GEMM D = xx_i + xx_j - 2 h h^T ---------------
// 128x128 output tile, 8x8 micro-tile (as 8x4 f32x2 pairs), 16x16 threads.
__global__ __launch_bounds__(256) void dist_kernel(const float* __restrict__ h,
                                                   const float* __restrict__ xx,
                                                   float* __restrict__ D) {
    __shared__ float As[128*17];   // [i][k], pad 17
    __shared__ float Bs[16*128];   // [k][j]
    int b = blockIdx.z;
    int i0 = blockIdx.y * 128, j0 = blockIdx.x * 128;
    const float* hb = h + (size_t)b * Nn * HD;
    int tid = threadIdx.x;
    int tx = tid & 15, ty = tid >> 4;

    u64t accp[8][4];
#pragma unroll
    for (int u = 0; u < 8; u++)
#pragma unroll
        for (int v = 0; v < 4; v++) accp[u][v] = 0ull;

    for (int k0 = 0; k0 < HD; k0 += 16) {
        __syncthreads();
#pragma unroll
        for (int pass = 0; pass < 2; pass++) {
            int f = tid + pass * 256;            // 0..511 float4 slots (128 rows x 4)
            int ri = f >> 2, rk = (f & 3) << 2;
            float4 va = *(const float4*)&hb[(i0 + ri)*HD + k0 + rk];
            As[ri*17 + rk + 0] = va.x; As[ri*17 + rk + 1] = va.y;
            As[ri*17 + rk + 2] = va.z; As[ri*17 + rk + 3] = va.w;
            float4 vb = *(const float4*)&hb[(j0 + ri)*HD + k0 + rk];
            Bs[(rk+0)*128 + ri] = vb.x; Bs[(rk+1)*128 + ri] = vb.y;
            Bs[(rk+2)*128 + ri] = vb.z; Bs[(rk+3)*128 + ri] = vb.w;
        }
        __syncthreads();
#pragma unroll
        for (int k = 0; k < 16; k++) {
            u64t a2[8];
#pragma unroll
            for (int u = 0; u < 8; u++) a2[u] = dup2(As[(ty*8 + u)*17 + k]);
            ulonglong2 q0 = *(const ulonglong2*)&Bs[k*128 + tx*8];
            ulonglong2 q1 = *(const ulonglong2*)&Bs[k*128 + tx*8 + 4];
            u64t bp[4] = {q0.x, q0.y, q1.x, q1.y};
#pragma unroll
            for (int u = 0; u < 8; u++)
#pragma unroll
                for (int v = 0; v < 4; v++) accp[u][v] = fma2(a2[u], bp[v], accp[u][v]);
        }
    }

    float xi[8], xj[8];
#pragma unroll
    for (int u = 0; u < 8; u++) xi[u] = xx[b*Nn + i0 + ty*8 + u];
#pragma unroll
    for (int v = 0; v < 8; v++) xj[v] = xx[b*Nn + j0 + tx*8 + v];
#pragma unroll
    for (int u = 0; u < 8; u++) {
        size_t base = ((size_t)b*Nn + i0 + ty*8 + u) * Nn + j0 + tx*8;
        float2 c0 = unpack2(accp[u][0]);
        float2 c1 = unpack2(accp[u][1]);
        float2 c2 = unpack2(accp[u][2]);
        float2 c3 = unpack2(accp[u][3]);
        float4 o0, o1;
        o0.x = xi[u] + xj[0] - 2.f*c0.x;
        o0.y = xi[u] + xj[1] - 2.f*c0.y;
        o0.z = xi[u] + xj[2] - 2.f*c1.x;
        o0.w = xi[u] + xj[3] - 2.f*c1.y;
        o1.x = xi[u] + xj[4] - 2.f*c2.x;
        o1.y = xi[u] + xj[5] - 2.f*c2.y;
        o1.z = xi[u] + xj[6] - 2.f*c3.x;
        o1.w = xi[u] + xj[7] - 2.f*c3.y;
        *(float4*)&D[base]     = o0;
        *(float4*)&D[base + 4] = o1;
    }
}

// ---------------- K4: top-16 via warp-collective bitonic running queue ------
__global__ __launch_bounds__(256) void topk_kernel(const float* __restrict__ D,
                                                   int* __restrict__ idxout) {
    const unsigned FULL = 0xffffffffu;
    int w = threadIdx.x >> 5, lane = threadIdx.x & 31;
    int row = blockIdx.x * 8 + w;
    const float* Dr = D + (size_t)row * Nn;

    const unsigned long long UMAX = 0xFFFFFFFFFFFFFFFFull;
    unsigned long long wq  = UMAX;   // lane i holds i-th smallest so far
    unsigned long long kth = UMAX;   // broadcast of wq at lane 15

    for (int t = 0; t < Nn / 128; t++) {
        float4 dv = *(const float4*)&Dr[t*128 + lane*4];
        float ds[4] = {dv.x, dv.y, dv.z, dv.w};
#pragma unroll
        for (int s = 0; s < 4; s++) {
            int j = t*128 + lane*4 + s;
            unsigned u = __float_as_uint(ds[s]);
            u ^= (unsigned)(((int)u >> 31)) | 0x80000000u;   // monotone float->uint
            unsigned long long key = ((unsigned long long)u << 32) | (unsigned)j;

            bool act = key < kth;
            if (__ballot_sync(FULL, act)) {
                unsigned long long c = act ? key : UMAX;

                // bitonic full sort of candidate batch, ascending across lanes
#pragma unroll
                for (int k = 2; k <= 32; k <<= 1) {
#pragma unroll
                    for (int jj = k >> 1; jj >= 1; jj >>= 1) {
                        unsigned long long p = __shfl_xor_sync(FULL, c, jj);
                        bool up = ((lane & k) == 0);
                        bool keepmin = (((lane & jj) == 0) == up);
                        c = keepmin ? u64min(c, p) : u64max(c, p);
                    }
                }

                // bitonic merge: keep smallest 32 of (sorted wq, sorted c)
                unsigned long long rev = __shfl_sync(FULL, c, 31 - lane);
                unsigned long long v = u64min(wq, rev);   // bitonic sequence
#pragma unroll
                for (int off = 16; off >= 1; off >>= 1) {
                    unsigned long long p = __shfl_xor_sync(FULL, v, off);
                    v = ((lane & off) == 0) ? u64min(v, p) : u64max(v, p);
                }
                wq = v;
                kth = __shfl_sync(FULL, wq, 15);
            }
        }
    }

    if (lane < Kk) idxout[row * Kk + lane] = (int)(wq & 0xFFFFFFFFull);
}

// ---------------- K5: fused edge MLP, xi/xj-decomposed ----------------------
// msg@W1 = xi@(W1a-W1b) + xj@W1b  ->  per-point P = b1 + xi@(W1a-W1b) computed
// once (8 points), per-edge GEMM1 reduced to k=64 against gathered Xj.
// smem floats: W1b 8192, W2 8192, Xj 128x68=8704, M1 16384, P 1024, Xi 512,
//              b1 128, b2 64  = 43200 floats (~173KB)
#define EDGE_SMEM_FLOATS (8192 + 8192 + 8704 + 16384 + 1024 + 512 + 128 + 64)
#define EDGE_SMEM_BYTES  (EDGE_SMEM_FLOATS * 4)

__global__ __launch_bounds__(256, 1) void edge_mlp_kernel(
    const float* __restrict__ h, const int* __restrict__ nidx,
    const float* __restrict__ W1, const float* __restrict__ b1,
    const float* __restrict__ W2, const float* __restrict__ b2,
    float* __restrict__ hout) {
    extern __shared__ float sm[];
    float* sW1b = sm;                  // [64][128] bottom half of W1
    float* sW2  = sW1b + 8192;         // [128][64]
    float* sXj  = sW2 + 8192;          // [128 edges][68]
    float* sM1  = sXj + 8704;          // [128][128]
    float* sP   = sM1 + 16384;         // [8][128] per-point precomp
    float* sXi  = sP + 1024;           // [8][64]
    float* sb1  = sXi + 512;
    float* sb2  = sb1 + 128;
    float* sWd  = sM1;                 // alias: W1a-W1b, dead before sM1 writes
    int*   sIdx = (int*)(sM1 + 8192);  // alias: dead before sM1 writes
    float* sHn  = sXj;                 // alias: dead after GEMM1 reads finish

    int tid = threadIdx.x;
    int b = blockIdx.y;
    int p0 = blockIdx.x * 8;
    const float* hb = h + (size_t)b * Nn * HD;

    // cooperative loads: W1b, Wd = W1a - W1b, W2, Xi, biases, idx
    {
        const float4* w1v = (const float4*)W1;
        float4* w1bv = (float4*)sW1b;
        float4* wdv  = (float4*)sWd;
        for (int f = tid; f < 2048; f += 256) {
            float4 a = w1v[f];          // W1a rows 0..63
            float4 c = w1v[f + 2048];   // W1b rows 64..127
            w1bv[f] = c;
            wdv[f] = make_float4(a.x-c.x, a.y-c.y, a.z-c.z, a.w-c.w);
        }
        const float4* w2v = (const float4*)W2;
        float4* s2v = (float4*)sW2;
        for (int f = tid; f < 2048; f += 256) s2v[f] = w2v[f];
        if (tid < 128) {   // Xi tile: 8 points x 64 = 128 float4
            int p = tid >> 4, q = tid & 15;
            *(float4*)&sXi[p*64 + q*4] = *(const float4*)&hb[(p0 + p)*HD + q*4];
        }
        if (tid < 128) sb1[tid] = b1[tid];
        if (tid < 64)  sb2[tid] = b2[tid];
        if (tid < 128) sIdx[tid] = nidx[((size_t)b*Nn + p0)*Kk + tid];
    }
    __syncthreads();

    // P[p][n] = b1[n] + sum_k Xi[p][k] * Wd[k][n]   (each thread: 4 outputs)
    {
        int p = tid >> 5, n0 = (tid & 31) * 4;
        float4 a = *(const float4*)&sb1[n0];
#pragma unroll 8
        for (int k = 0; k < 64; k++) {
            float xv = sXi[p*64 + k];
            float4 wv = *(const float4*)&sWd[k*128 + n0];
            a.x = fmaf(xv, wv.x, a.x);
            a.y = fmaf(xv, wv.y, a.y);
            a.z = fmaf(xv, wv.z, a.z);
            a.w = fmaf(xv, wv.w, a.w);
        }
        *(float4*)&sP[p*128 + n0] = a;
    }
    // gather Xj (128 edges x 64)
    for (int f = tid; f < 2048; f += 256) {
        int e = f >> 4, q = f & 15;
        int j = sIdx[e];
        *(float4*)&sXj[e*68 + q*4] = *(const float4*)&hb[j*HD + q*4];
    }
    __syncthreads();

    int tx = tid & 15, ty = tid >> 4;
    int pA = ty >> 2;     // first-half point; second half = pA+4

    // GEMM1: m1 = elu(P[pt] + Xj @ W1b)   (128 edges x 128 out x k=64), f32x2
    u64t accp[8][4];
    {
        ulonglong2 i0 = *(const ulonglong2*)&sP[pA*128 + tx*8];
        ulonglong2 i1 = *(const ulonglong2*)&sP[pA*128 + tx*8 + 4];
        ulonglong2 i2 = *(const ulonglong2*)&sP[(pA+4)*128 + tx*8];
        ulonglong2 i3 = *(const ulonglong2*)&sP[(pA+4)*128 + tx*8 + 4];
#pragma unroll
        for (int u = 0; u < 4; u++) {
            accp[u][0] = i0.x; accp[u][1] = i0.y; accp[u][2] = i1.x; accp[u][3] = i1.y;
            accp[4+u][0] = i2.x; accp[4+u][1] = i2.y; accp[4+u][2] = i3.x; accp[4+u][3] = i3.y;
        }
    }
    {
        const float* aB = sXj + (ty*4)*68;   // rows ty*4..+3 and +64..+67
#pragma unroll 4
        for (int k = 0; k < 64; k++) {
            u64t a2[8];
#pragma unroll
            for (int u = 0; u < 4; u++) a2[u]   = dup2(aB[u*68 + k]);
#pragma unroll
            for (int u = 0; u < 4; u++) a2[4+u] = dup2(aB[(64+u)*68 + k]);
            ulonglong2 q0 = *(const ulonglong2*)&sW1b[k*128 + tx*8];
            ulonglong2 q1 = *(const ulonglong2*)&sW1b[k*128 + tx*8 + 4];
            u64t bp[4] = {q0.x, q0.y, q1.x, q1.y};
#pragma unroll
            for (int u = 0; u < 8; u++)
#pragma unroll
                for (int v = 0; v < 4; v++) accp[u][v] = fma2(a2[u], bp[v], accp[u][v]);
        }
    }
    // epilogue -> sM1 (elu only; bias already in P)
#pragma unroll
    for (int u = 0; u < 8; u++) {
        int r = ty*4 + (u & 3) + ((u >> 2) << 6);
        float2 c0 = unpack2(accp[u][0]);
        float2 c1 = unpack2(accp[u][1]);
        float2 c2 = unpack2(accp[u][2]);
        float2 c3 = unpack2(accp[u][3]);
        float4 s0, s1;
        s0.x = elu1(c0.x); s0.y = elu1(c0.y); s0.z = elu1(c1.x); s0.w = elu1(c1.y);
        s1.x = elu1(c2.x); s1.y = elu1(c2.y); s1.z = elu1(c3.x); s1.w = elu1(c3.y);
        *(float4*)&sM1[r*128 + tx*8]     = s0;
        *(float4*)&sM1[r*128 + tx*8 + 4] = s1;
    }
    __syncthreads();           // sM1 complete, sXj reads done
    sHn[tid] = 0.f; sHn[tid + 256] = 0.f;
    __syncthreads();

    // GEMM2: m2 = elu(m1 @ W2 + b2), summed over K=16 edges per point (f32x2)
    u64t accp2[8][2];
#pragma unroll
    for (int u = 0; u < 8; u++)
#pragma unroll
        for (int v = 0; v < 2; v++) accp2[u][v] = 0ull;
    {
        const float* aB = sM1 + (ty*4)*128;
#pragma unroll 4
        for (int k = 0; k < 128; k++) {
            u64t a2[8];
#pragma unroll
            for (int u = 0; u < 4; u++) a2[u]   = dup2(aB[u*128 + k]);
#pragma unroll
            for (int u = 0; u < 4; u++) a2[4+u] = dup2(aB[(64+u)*128 + k]);
            ulonglong2 q = *(const ulonglong2*)&sW2[k*64 + tx*4];
            u64t bp[2] = {q.x, q.y};
#pragma unroll
            for (int u = 0; u < 8; u++)
#pragma unroll
                for (int v = 0; v < 2; v++) accp2[u][v] = fma2(a2[u], bp[v], accp2[u][v]);
        }
    }
    {
#pragma unroll
        for (int half = 0; half < 2; half++) {
            int p = pA + half*4;
#pragma unroll
            for (int vp = 0; vp < 2; vp++) {
                float slo = 0.f, shi = 0.f;
#pragma unroll
                for (int u0 = 0; u0 < 4; u0++) {
                    float2 c = unpack2(accp2[half*4 + u0][vp]);
                    slo += elu1(c.x + sb2[tx*4 + 2*vp]);
                    shi += elu1(c.y + sb2[tx*4 + 2*vp + 1]);
                }
                atomicAdd(&sHn[p*64 + tx*4 + 2*vp],     slo);
                atomicAdd(&sHn[p*64 + tx*4 + 2*vp + 1], shi);
            }
        }
    }
    __syncthreads();
    for (int f = tid; f < 512; f += 256) {
        int p = f >> 6, c = f & 63;
        hout[((size_t)b*Nn + p0 + p)*HD + c] = sHn[f];
    }
}

// ---------------- K6: max-pool + 3-layer head -------------------------------
__global__ __launch_bounds__(256) void pool_head_kernel(const float* __restrict__ h,
    const float* __restrict__ Wo1, const float* __restrict__ bo1,
    const float* __restrict__ Wo2, const float* __restrict__ bo2,
    const float* __restrict__ Wo3, const float* __restrict__ bo3,
    float* __restrict__ out) {
    __shared__ float red[256];
    __shared__ float sp[64];
    __shared__ float so[64];
    int b = blockIdx.x, tid = threadIdx.x;
    int c = tid & 63, g = tid >> 6;
    const float* hb = h + (size_t)b * Nn * HD;
    float m = -3.402823e38f;
    for (int n = g; n < Nn; n += 4) m = fmaxf(m, hb[n*HD + c]);
    red[tid] = m;
    __syncthreads();
    if (tid < 64)
        sp[tid] = fmaxf(fmaxf(red[tid], red[tid+64]), fmaxf(red[tid+128], red[tid+192]));
    __syncthreads();
    if (tid < 64) {
        float a = bo1[tid];
#pragma unroll 8
        for (int d = 0; d < 64; d++) a = fmaf(sp[d], Wo1[d*64 + tid], a);
        so[tid] = elu1(a);
    }
    __syncthreads();
    if (tid < 64) {
        float a = bo2[tid];
#pragma unroll 8
        for (int d = 0; d < 64; d++) a = fmaf(so[d], Wo2[d*64 + tid], a);
        red[tid] = elu1(a);
    }
    __syncthreads();
    if (tid == 0) {
        float a = bo3[0];
#pragma unroll 8
        for (int d = 0; d < 64; d++) a = fmaf(red[d], Wo3[d], a);
        out[b] = a;
    }
}

// ---------------- launcher --------------------------------------------------
extern "C" void kernel_launch(void* const* d_in, const int* in_sizes, int n_in,
                              void* d_out, int out_size) {
    const float* x   = (const float*)d_in[0];
    const float* dn  = (const float*)d_in[1];
    const float* Win = (const float*)d_in[2];
    const float* bin = (const float*)d_in[3];
    const float* W1  = (const float*)d_in[4];
    const float* b1  = (const float*)d_in[5];
    const float* W2  = (const float*)d_in[6];
    const float* b2  = (const float*)d_in[7];
    const float* Wo1 = (const float*)d_in[8];
    const float* bo1 = (const float*)d_in[9];
    const float* Wo2 = (const float*)d_in[10];
    const float* bo2 = (const float*)d_in[11];
    const float* Wo3 = (const float*)d_in[12];
    const float* bo3 = (const float*)d_in[13];
    float* out = (float*)d_out;

    float *ph, *phn, *pxx, *pD; int* pidx;
    cudaGetSymbolAddress((void**)&ph,  g_h);
    cudaGetSymbolAddress((void**)&phn, g_hn);
    cudaGetSymbolAddress((void**)&pxx, g_xx);
    cudaGetSymbolAddress((void**)&pD,  g_D);
    cudaGetSymbolAddress((void**)&pidx, g_idx);

    cudaFuncSetAttribute(edge_mlp_kernel,
                         cudaFuncAttributeMaxDynamicSharedMemorySize, EDGE_SMEM_BYTES);

    embed_kernel<<<(Bb*Nn*HD + 255)/256, 256>>>(x, dn, Win, bin, ph);

    for (int l = 0; l < Ll; l++) {
        const float* hin = (l == 0) ? ph : phn;
        float* hout      = (l == 0) ? phn : ph;
        xx_kernel<<<Bb*Nn/8, 256>>>(hin, pxx);
        dist_kernel<<<dim3(Nn/128, Nn/128, Bb), 256>>>(hin, pxx, pD);
        topk_kernel<<<Bb*Nn/8, 256>>>(pD, pidx);
        edge_mlp_kernel<<<dim3(Nn/8, Bb), 256, EDGE_SMEM_BYTES>>>(
            hin, pidx, W1 + l*2*HD*2*HD, b1 + l*2*HD, W2 + l*2*HD*HD, b2 + l*HD, hout);
    }

    pool_head_kernel<<<Bb, 256>>>(ph, Wo1, bo1, Wo2, bo2, Wo3, bo3, out);
}